// round 1
// baseline (speedup 1.0000x reference)
#include <cuda_runtime.h>
#include <cuda_bf16.h>
#include <math.h>

// ---------------------------------------------------------------------------
// Scratch layout (floats) inside one __device__ array:
//   y0: [4,160,160,64] NHWC   off 0
//   y1: [4, 80, 80,64]        off 6553600
//   y2: [4, 40, 40,64]        off 8192000
//   y3: [4, 20, 20,64]        off 8601600
//   X : [4,160,160,64]        off 8704000
//   om: [4,160,160,27]        off 15257600
//   Wt: [576,64]              off 18022400
// total 18059264 floats (~72 MB)
// ---------------------------------------------------------------------------
#define OFF_Y0 0
#define OFF_Y1 6553600
#define OFF_Y2 8192000
#define OFF_Y3 8601600
#define OFF_X  8704000
#define OFF_OM 15257600
#define OFF_WT 18022400
#define SCRATCH_TOTAL 18059264

__device__ float g_scratch[SCRATCH_TOTAL];

// ---------------------------------------------------------------------------
// Kernel 1: 1x1 conv + BN -> NHWC
// grid = B*HW blocks, 64 threads (one per out channel)
// ---------------------------------------------------------------------------
__global__ void conv1x1_bn_kernel(const float* __restrict__ f,
                                  const float* __restrict__ w,
                                  const float* __restrict__ g,
                                  const float* __restrict__ b,
                                  const float* __restrict__ m,
                                  const float* __restrict__ v,
                                  float* __restrict__ y,
                                  int cin, int HW) {
    int c   = threadIdx.x;                 // 0..63
    int pix = blockIdx.x;                  // b*HW + hw
    int bb  = pix / HW;
    int hw  = pix - bb * HW;
    const float* fp = f + (size_t)bb * cin * HW + hw;
    const float* wp = w + (size_t)c * cin;

    float a0 = 0.f, a1 = 0.f, a2 = 0.f, a3 = 0.f;
    for (int i = 0; i < cin; i += 4) {
        a0 += __ldg(fp + (size_t)(i + 0) * HW) * __ldg(wp + i + 0);
        a1 += __ldg(fp + (size_t)(i + 1) * HW) * __ldg(wp + i + 1);
        a2 += __ldg(fp + (size_t)(i + 2) * HW) * __ldg(wp + i + 2);
        a3 += __ldg(fp + (size_t)(i + 3) * HW) * __ldg(wp + i + 3);
    }
    float acc = (a0 + a1) + (a2 + a3);
    float sc = __ldg(g + c) * rsqrtf(__ldg(v + c) + 1e-5f);
    float bi = __ldg(b + c) - __ldg(m + c) * sc;
    y[(size_t)pix * 64 + c] = acc * sc + bi;
}

// ---------------------------------------------------------------------------
// Kernel 2: fused align-corners bilinear upsample + sum + relu -> X (NHWC)
// ---------------------------------------------------------------------------
__device__ __forceinline__ float bilerp_lvl(const float* __restrict__ y,
                                            int bb, int n, int h, int w, int c) {
    float r  = (float)(n - 1) / 159.0f;
    float sy = (float)h * r;
    float sx = (float)w * r;
    int iy = (int)sy; if (iy > n - 2) iy = n - 2;
    int ix = (int)sx; if (ix > n - 2) ix = n - 2;
    float ty = sy - (float)iy;
    float tx = sx - (float)ix;
    const float* base = y + ((((size_t)bb * n + iy) * n + ix) * 64) + c;
    float v00 = __ldg(base);
    float v01 = __ldg(base + 64);
    float v10 = __ldg(base + (size_t)n * 64);
    float v11 = __ldg(base + (size_t)n * 64 + 64);
    float top = v00 * (1.f - tx) + v01 * tx;
    float bot = v10 * (1.f - tx) + v11 * tx;
    return top * (1.f - ty) + bot * ty;
}

__global__ void fuse_kernel() {
    int c   = threadIdx.x;
    int pix = blockIdx.x;                  // b*25600 + h*160 + w
    int bb  = pix / 25600;
    int hw  = pix - bb * 25600;
    int h   = hw / 160;
    int w   = hw - h * 160;
    const float* y0 = g_scratch + OFF_Y0;
    const float* y1 = g_scratch + OFF_Y1;
    const float* y2 = g_scratch + OFF_Y2;
    const float* y3 = g_scratch + OFF_Y3;
    float acc = y0[(size_t)pix * 64 + c];
    acc += bilerp_lvl(y1, bb, 80, h, w, c);
    acc += bilerp_lvl(y2, bb, 40, h, w, c);
    acc += bilerp_lvl(y3, bb, 20, h, w, c);
    g_scratch[OFF_X + (size_t)pix * 64 + c] = fmaxf(acc, 0.f);
}

// ---------------------------------------------------------------------------
// Kernel 3: offset conv 3x3, 64 -> 27, pad 1, on X (NHWC) -> om (NHWC-27)
// block: 128 threads, tile of 16 consecutive w positions in one row
// ---------------------------------------------------------------------------
#define TW 16
__global__ __launch_bounds__(128) void offconv_kernel(const float* __restrict__ ow,
                                                      const float* __restrict__ ob) {
    __shared__ float patch[3 * 18 * 65];   // [(r*18+col)*65 + c], padded
    int tid = threadIdx.x;
    int w0  = blockIdx.x * TW;
    int h   = blockIdx.y;
    int bb  = blockIdx.z;
    const float* X  = g_scratch + OFF_X;
    float*       om = g_scratch + OFF_OM;

    // load 3x18x64 input patch (zero-padded at borders)
    for (int i = tid; i < 3 * 18 * 64; i += 128) {
        int c   = i & 63;
        int rc  = i >> 6;
        int col = rc % 18;
        int r   = rc / 18;
        int hh  = h + r - 1;
        int ww  = w0 + col - 1;
        float val = 0.f;
        if (hh >= 0 && hh < 160 && ww >= 0 && ww < 160)
            val = X[((((size_t)bb * 160 + hh) * 160 + ww) * 64) + c];
        patch[(r * 18 + col) * 65 + c] = val;
    }
    __syncthreads();

    // 27*16 = 432 outputs
    for (int oi = tid; oi < 27 * TW; oi += 128) {
        int p  = oi & 15;
        int kk = oi >> 4;
        float acc = __ldg(ob + kk);
        const float* wk = ow + (size_t)kk * 576;   // [c][ky][kx]
        for (int c = 0; c < 64; c++) {
            #pragma unroll
            for (int ky = 0; ky < 3; ky++) {
                #pragma unroll
                for (int kx = 0; kx < 3; kx++) {
                    acc += patch[(ky * 18 + p + kx) * 65 + c] * __ldg(wk + c * 9 + ky * 3 + kx);
                }
            }
        }
        om[(((size_t)bb * 160 + h) * 160 + (w0 + p)) * 27 + kk] = acc;
    }
}

// ---------------------------------------------------------------------------
// Kernel: transpose dcn weights [64][64*9] -> Wt[ck][64]
// ---------------------------------------------------------------------------
__global__ void wtrans_kernel(const float* __restrict__ dw) {
    int i = blockIdx.x * 256 + threadIdx.x;
    if (i < 64 * 576) {
        int o  = i / 576;
        int ck = i - o * 576;
        g_scratch[OFF_WT + (size_t)ck * 64 + o] = dw[i];
    }
}

// ---------------------------------------------------------------------------
// Kernel 4: DCNv2 (gather + GEMM) + BN + relu -> d_out (NCHW)
// block: 64 threads, 8 consecutive w pixels
// ---------------------------------------------------------------------------
__global__ __launch_bounds__(64) void dcn_kernel(const float* __restrict__ gf,
                                                 const float* __restrict__ bfp,
                                                 const float* __restrict__ mf,
                                                 const float* __restrict__ vf,
                                                 float* __restrict__ out) {
    __shared__ float ssy[8][9], ssx[8][9], smk[8][9];
    __shared__ float valS[8 * 576];        // [p][c*9+k]
    int tid = threadIdx.x;                 // 64
    int w0  = blockIdx.x * 8;
    int h   = blockIdx.y;
    int bb  = blockIdx.z;
    const float* X  = g_scratch + OFF_X;
    const float* om = g_scratch + OFF_OM;
    const float* wt = g_scratch + OFF_WT;

    // phase 0: decode offsets + masks for the 8 pixels x 9 taps
    for (int i = tid; i < 72; i += 64) {
        int p = i / 9, k = i - (i / 9) * 9;
        size_t base = ((((size_t)bb * 160 + h) * 160) + (w0 + p)) * 27;
        float dy = om[base + 2 * k];
        float dx = om[base + 2 * k + 1];
        float mk = om[base + 18 + k];
        smk[p][k] = 1.f / (1.f + expf(-mk));
        ssy[p][k] = (float)h + (float)(k / 3 - 1) + dy;
        ssx[p][k] = (float)(w0 + p) + (float)(k % 3 - 1) + dx;
    }
    __syncthreads();

    // phase 1: gather (thread = channel c)
    {
        int c = tid;
        const float* Xb = X + (size_t)bb * 25600 * 64;
        for (int p = 0; p < 8; p++) {
            #pragma unroll
            for (int k = 0; k < 9; k++) {
                float syv = ssy[p][k];
                float sxv = ssx[p][k];
                float fy = floorf(syv), fx = floorf(sxv);
                float ty = syv - fy, tx = sxv - fx;
                int iy = (int)fy, ix = (int)fx;
                float v = 0.f;
                #pragma unroll
                for (int d2 = 0; d2 < 2; d2++) {
                    int yy = iy + d2;
                    float wy = d2 ? ty : (1.f - ty);
                    bool vy = (yy >= 0) && (yy < 160);
                    int cy = yy < 0 ? 0 : (yy > 159 ? 159 : yy);
                    #pragma unroll
                    for (int d3 = 0; d3 < 2; d3++) {
                        int xx = ix + d3;
                        float wx = d3 ? tx : (1.f - tx);
                        bool vx = (xx >= 0) && (xx < 160);
                        int cx = xx < 0 ? 0 : (xx > 159 ? 159 : xx);
                        float gval = __ldg(Xb + ((size_t)cy * 160 + cx) * 64 + c);
                        v += gval * (wy * wx * ((vy && vx) ? 1.f : 0.f));
                    }
                }
                valS[p * 576 + c * 9 + k] = v * smk[p][k];
            }
        }
    }
    __syncthreads();

    // phase 2: GEMM (thread = output channel o), 8 pixels per block
    int o = tid;
    float acc[8] = {0.f, 0.f, 0.f, 0.f, 0.f, 0.f, 0.f, 0.f};
    #pragma unroll 4
    for (int ck = 0; ck < 576; ck++) {
        float wv = __ldg(wt + (size_t)ck * 64 + o);
        #pragma unroll
        for (int p = 0; p < 8; p++)
            acc[p] += valS[p * 576 + ck] * wv;
    }
    __syncthreads();

    // phase 3: BN + relu, stage to shared, coalesced NCHW store
    float sc = __ldg(gf + o) * rsqrtf(__ldg(vf + o) + 1e-5f);
    float bi = __ldg(bfp + o) - __ldg(mf + o) * sc;
    float* outS = valS;
    #pragma unroll
    for (int p = 0; p < 8; p++)
        outS[o * 8 + p] = fmaxf(acc[p] * sc + bi, 0.f);
    __syncthreads();
    for (int i = tid; i < 512; i += 64) {
        int oo = i >> 3;
        int p  = i & 7;
        out[((((size_t)bb * 64 + oo) * 160 + h) * 160) + w0 + p] = outS[i];
    }
}

// ---------------------------------------------------------------------------
// launch
// ---------------------------------------------------------------------------
extern "C" void kernel_launch(void* const* d_in, const int* in_sizes, int n_in,
                              void* d_out, int out_size) {
    const float* f0 = (const float*)d_in[0];
    const float* f1 = (const float*)d_in[1];
    const float* f2 = (const float*)d_in[2];
    const float* f3 = (const float*)d_in[3];
    const float* w0 = (const float*)d_in[4];
    const float* g0 = (const float*)d_in[5];
    const float* b0 = (const float*)d_in[6];
    const float* m0 = (const float*)d_in[7];
    const float* v0 = (const float*)d_in[8];
    const float* w1 = (const float*)d_in[9];
    const float* g1 = (const float*)d_in[10];
    const float* b1 = (const float*)d_in[11];
    const float* m1 = (const float*)d_in[12];
    const float* v1 = (const float*)d_in[13];
    const float* w2 = (const float*)d_in[14];
    const float* g2 = (const float*)d_in[15];
    const float* b2 = (const float*)d_in[16];
    const float* m2 = (const float*)d_in[17];
    const float* v2 = (const float*)d_in[18];
    const float* w3 = (const float*)d_in[19];
    const float* g3 = (const float*)d_in[20];
    const float* b3 = (const float*)d_in[21];
    const float* m3 = (const float*)d_in[22];
    const float* v3 = (const float*)d_in[23];
    const float* off_w = (const float*)d_in[24];
    const float* off_b = (const float*)d_in[25];
    const float* dcn_w = (const float*)d_in[26];
    const float* gf = (const float*)d_in[27];
    const float* bf = (const float*)d_in[28];
    const float* mf = (const float*)d_in[29];
    const float* vf = (const float*)d_in[30];
    float* out = (float*)d_out;

    float* scratch = nullptr;
    cudaGetSymbolAddress((void**)&scratch, g_scratch);

    // 1x1 conv + BN per level (NHWC outputs)
    conv1x1_bn_kernel<<<4 * 160 * 160, 64>>>(f0, w0, g0, b0, m0, v0,
                                             scratch + OFF_Y0, 64, 160 * 160);
    conv1x1_bn_kernel<<<4 * 80 * 80, 64>>>(f1, w1, g1, b1, m1, v1,
                                           scratch + OFF_Y1, 128, 80 * 80);
    conv1x1_bn_kernel<<<4 * 40 * 40, 64>>>(f2, w2, g2, b2, m2, v2,
                                           scratch + OFF_Y2, 256, 40 * 40);
    conv1x1_bn_kernel<<<4 * 20 * 20, 64>>>(f3, w3, g3, b3, m3, v3,
                                           scratch + OFF_Y3, 512, 20 * 20);

    // fused upsample + sum + relu
    fuse_kernel<<<4 * 160 * 160, 64>>>();

    // dcn weight transpose
    wtrans_kernel<<<(64 * 576 + 255) / 256, 256>>>(dcn_w);

    // offset conv
    offconv_kernel<<<dim3(160 / TW, 160, 4), 128>>>(off_w, off_b);

    // deformable conv + final BN + relu
    dcn_kernel<<<dim3(160 / 8, 160, 4), 64>>>(gf, bf, mf, vf, out);
}

// round 5
// speedup vs baseline: 3.3862x; 3.3862x over previous
#include <cuda_runtime.h>
#include <cuda_bf16.h>
#include <math.h>

// ---------------------------------------------------------------------------
// Scratch layout (floats):
//   y0: [4,160,160,64] NHWC   off 0
//   y1: [4, 80, 80,64]        off 6553600
//   y2: [4, 40, 40,64]        off 8192000
//   y3: [4, 20, 20,64]        off 8601600
//   X : [4,160,160,64]        off 8704000
//   om: [4,160,160,27]        off 15257600
//   Wt: [(k*64+c)][64 o]      off 18022400   (36864)
// ---------------------------------------------------------------------------
#define OFF_Y0 0
#define OFF_Y1 6553600
#define OFF_Y2 8192000
#define OFF_Y3 8601600
#define OFF_X  8704000
#define OFF_OM 15257600
#define OFF_WT 18022400
#define SCRATCH_TOTAL 18059264

__device__ __align__(16) float g_scratch[SCRATCH_TOTAL];

// ---------------------------------------------------------------------------
// Kernel 1: 1x1 conv + BN as tiled SGEMM -> NHWC
// block 256 threads, tile: 64 out-ch x 64 pixels, K-tile 16
// ---------------------------------------------------------------------------
__global__ __launch_bounds__(256) void conv1x1_bn_v2(
    const float* __restrict__ f, const float* __restrict__ w,
    const float* __restrict__ g, const float* __restrict__ b,
    const float* __restrict__ m, const float* __restrict__ v,
    float* __restrict__ y, int cin, int HW) {
    __shared__ __align__(16) float Wsh[16 * 68];   // [kt][cout] pad 68
    __shared__ __align__(16) float Insh[16 * 64];  // [kt][p]

    int tid = threadIdx.x;
    int hw0 = blockIdx.x * 64;
    int bb  = blockIdx.y;
    const float* fb = f + (size_t)bb * cin * HW;

    int tx = tid & 15;     // pixel group
    int ty = tid >> 4;     // cout group
    float acc[4][4];
    #pragma unroll
    for (int j = 0; j < 4; j++)
        #pragma unroll
        for (int i = 0; i < 4; i++) acc[j][i] = 0.f;

    for (int k0 = 0; k0 < cin; k0 += 16) {
        // stage W tile [64 cout][16 k] -> Wsh[kt][cout]
        {
            int c  = tid >> 2;
            int kt = (tid & 3) * 4;
            float4 wv = *(const float4*)(w + (size_t)c * cin + k0 + kt);
            Wsh[(kt + 0) * 68 + c] = wv.x;
            Wsh[(kt + 1) * 68 + c] = wv.y;
            Wsh[(kt + 2) * 68 + c] = wv.z;
            Wsh[(kt + 3) * 68 + c] = wv.w;
        }
        // stage In tile [16 k][64 px]
        {
            int kt = tid >> 4;
            int p  = (tid & 15) * 4;
            float4 iv = make_float4(0.f, 0.f, 0.f, 0.f);
            if (hw0 + p < HW)
                iv = *(const float4*)(fb + (size_t)(k0 + kt) * HW + hw0 + p);
            *(float4*)(Insh + kt * 64 + p) = iv;
        }
        __syncthreads();
        #pragma unroll
        for (int kt = 0; kt < 16; kt++) {
            float4 wv = *(const float4*)(Wsh + kt * 68 + ty * 4);
            float4 xv = *(const float4*)(Insh + kt * 64 + tx * 4);
            acc[0][0] += xv.x * wv.x; acc[0][1] += xv.x * wv.y;
            acc[0][2] += xv.x * wv.z; acc[0][3] += xv.x * wv.w;
            acc[1][0] += xv.y * wv.x; acc[1][1] += xv.y * wv.y;
            acc[1][2] += xv.y * wv.z; acc[1][3] += xv.y * wv.w;
            acc[2][0] += xv.z * wv.x; acc[2][1] += xv.z * wv.y;
            acc[2][2] += xv.z * wv.z; acc[2][3] += xv.z * wv.w;
            acc[3][0] += xv.w * wv.x; acc[3][1] += xv.w * wv.y;
            acc[3][2] += xv.w * wv.z; acc[3][3] += xv.w * wv.w;
        }
        __syncthreads();
    }

    int cb = ty * 4;
    float sc[4], bi[4];
    #pragma unroll
    for (int i = 0; i < 4; i++) {
        sc[i] = __ldg(g + cb + i) * rsqrtf(__ldg(v + cb + i) + 1e-5f);
        bi[i] = __ldg(b + cb + i) - __ldg(m + cb + i) * sc[i];
    }
    #pragma unroll
    for (int j = 0; j < 4; j++) {
        int hw = hw0 + tx * 4 + j;
        if (hw < HW) {
            float4 ov;
            ov.x = acc[j][0] * sc[0] + bi[0];
            ov.y = acc[j][1] * sc[1] + bi[1];
            ov.z = acc[j][2] * sc[2] + bi[2];
            ov.w = acc[j][3] * sc[3] + bi[3];
            *(float4*)(y + ((size_t)bb * HW + hw) * 64 + cb) = ov;
        }
    }
}

// ---------------------------------------------------------------------------
// Kernel 2: fused bilinear upsample + sum + relu (float4 over channels)
// block 64 threads = 4 pixels x 16 c4-groups
// ---------------------------------------------------------------------------
__device__ __forceinline__ float4 bilerp4(const float* __restrict__ y,
                                          int bb, int n, int h, int w, int c) {
    float r  = (float)(n - 1) / 159.0f;
    float sy = (float)h * r;
    float sx = (float)w * r;
    int iy = (int)sy; if (iy > n - 2) iy = n - 2;
    int ix = (int)sx; if (ix > n - 2) ix = n - 2;
    float ty = sy - (float)iy;
    float tx = sx - (float)ix;
    const float* base = y + ((((size_t)bb * n + iy) * n + ix) * 64) + c;
    float4 v00 = *(const float4*)(base);
    float4 v01 = *(const float4*)(base + 64);
    float4 v10 = *(const float4*)(base + (size_t)n * 64);
    float4 v11 = *(const float4*)(base + (size_t)n * 64 + 64);
    float4 o;
    o.x = (v00.x * (1.f - tx) + v01.x * tx) * (1.f - ty) + (v10.x * (1.f - tx) + v11.x * tx) * ty;
    o.y = (v00.y * (1.f - tx) + v01.y * tx) * (1.f - ty) + (v10.y * (1.f - tx) + v11.y * tx) * ty;
    o.z = (v00.z * (1.f - tx) + v01.z * tx) * (1.f - ty) + (v10.z * (1.f - tx) + v11.z * tx) * ty;
    o.w = (v00.w * (1.f - tx) + v01.w * tx) * (1.f - ty) + (v10.w * (1.f - tx) + v11.w * tx) * ty;
    return o;
}

__global__ __launch_bounds__(64) void fuse_v2() {
    int tid = threadIdx.x;
    int c4  = (tid & 15) * 4;
    int pix = blockIdx.x * 4 + (tid >> 4);
    int bb  = pix / 25600;
    int hw  = pix - bb * 25600;
    int h   = hw / 160;
    int w   = hw - h * 160;
    const float* y0 = g_scratch + OFF_Y0;
    float4 a = *(const float4*)(y0 + (size_t)pix * 64 + c4);
    float4 t;
    t = bilerp4(g_scratch + OFF_Y1, bb, 80, h, w, c4); a.x += t.x; a.y += t.y; a.z += t.z; a.w += t.w;
    t = bilerp4(g_scratch + OFF_Y2, bb, 40, h, w, c4); a.x += t.x; a.y += t.y; a.z += t.z; a.w += t.w;
    t = bilerp4(g_scratch + OFF_Y3, bb, 20, h, w, c4); a.x += t.x; a.y += t.y; a.z += t.z; a.w += t.w;
    a.x = fmaxf(a.x, 0.f); a.y = fmaxf(a.y, 0.f);
    a.z = fmaxf(a.z, 0.f); a.w = fmaxf(a.w, 0.f);
    *(float4*)(g_scratch + OFF_X + (size_t)pix * 64 + c4) = a;
}

// ---------------------------------------------------------------------------
// Kernel 3: offset conv 3x3, 64->27. Tile: 1 row x 32 px. 128 threads.
// Weights staged in smem, patch [c][ky][col36].
// NOTE: patch base index padded to 15580 (multiple of 4) so float4 loads on
// a 16B-aligned base — 15579 caused the round-4 misaligned-address fault.
// ---------------------------------------------------------------------------
#define OFFC_WPAD 15580
#define OFFC_SMEM ((OFFC_WPAD + 64 * 3 * 36) * 4)
__global__ __launch_bounds__(128) void offconv_v2(const float* __restrict__ ow,
                                                  const float* __restrict__ ob) {
    extern __shared__ __align__(16) float sm[];
    float* Wsh   = sm;                 // 27*577 used
    float* patch = sm + OFFC_WPAD;     // 64*3*36, 16B-aligned base

    int tid = threadIdx.x;
    int w0  = blockIdx.x * 32;
    int h   = blockIdx.y;
    int bb  = blockIdx.z;
    const float* X  = g_scratch + OFF_X;
    float*       om = g_scratch + OFF_OM;

    // stage weights [27][576] with pad-577 rows
    for (int i = tid; i < 27 * 576; i += 128) {
        int kk = i / 576;
        Wsh[kk * 577 + (i - kk * 576)] = ow[i];
    }
    // stage patch: rows h-1..h+1, cols w0-1..w0+32 (34), layout [c][r][col36]
    for (int i = tid; i < 64 * 3 * 34; i += 128) {
        int c    = i & 63;
        int rest = i >> 6;
        int col  = rest % 34;
        int r    = rest / 34;
        int hh = h + r - 1;
        int ww = w0 + col - 1;
        float val = 0.f;
        if (hh >= 0 && hh < 160 && ww >= 0 && ww < 160)
            val = X[((((size_t)bb * 160 + hh) * 160 + ww) * 64) + c];
        patch[(c * 3 + r) * 36 + col] = val;
    }
    __syncthreads();

    int kk = tid & 31;
    int p0 = (tid >> 5) * 8;
    if (kk < 27) {
        float bias = __ldg(ob + kk);
        float acc[8];
        #pragma unroll
        for (int j = 0; j < 8; j++) acc[j] = bias;
        const float* wrow = Wsh + kk * 577;
        for (int c = 0; c < 64; c++) {
            #pragma unroll
            for (int r = 0; r < 3; r++) {
                const float* prow = patch + (c * 3 + r) * 36 + p0;
                float4 t0 = *(const float4*)(prow);
                float4 t1 = *(const float4*)(prow + 4);
                float2 t2 = *(const float2*)(prow + 8);
                float tt[10] = {t0.x, t0.y, t0.z, t0.w, t1.x, t1.y, t1.z, t1.w, t2.x, t2.y};
                #pragma unroll
                for (int kx = 0; kx < 3; kx++) {
                    float wv = wrow[c * 9 + r * 3 + kx];
                    #pragma unroll
                    for (int j = 0; j < 8; j++) acc[j] += tt[j + kx] * wv;
                }
            }
        }
        #pragma unroll
        for (int j = 0; j < 8; j++)
            om[((((size_t)bb * 160 + h) * 160) + (w0 + p0 + j)) * 27 + kk] = acc[j];
    }
}

// ---------------------------------------------------------------------------
// Kernel: transpose dcn weights -> Wt[(k*64+c)*64 + o]
// ---------------------------------------------------------------------------
__global__ void wtrans_v2(const float* __restrict__ dw) {
    int i = blockIdx.x * 256 + threadIdx.x;   // 36864
    if (i < 36864) {
        int o   = i & 63;
        int row = i >> 6;          // k*64 + c
        int k   = row >> 6;
        int c   = row & 63;
        g_scratch[OFF_WT + i] = dw[(size_t)o * 576 + c * 9 + k];
    }
}

// ---------------------------------------------------------------------------
// Kernel 4: DCNv2 gather + GEMM + BN + relu. 32 px/block, 128 threads.
// val smem layout: [(k*32+p)*68 + c]  (c padded to 68)
// GEMM microtile 4o x 4px, weight via coalesced LDG.128 from Wt.
// ---------------------------------------------------------------------------
#define DCN_SMEM ((864 + 288 * 68) * 4)
__global__ __launch_bounds__(128) void dcn_v2(const float* __restrict__ gf,
                                              const float* __restrict__ bfp,
                                              const float* __restrict__ mf,
                                              const float* __restrict__ vf,
                                              float* __restrict__ out) {
    extern __shared__ __align__(16) float sm[];
    float* ssy = sm;          // [32*9]
    float* ssx = sm + 288;
    float* smk = sm + 576;
    float* val = sm + 864;    // 288 rows * 68, 16B-aligned base (864%4==0)

    int tid = threadIdx.x;
    int w0  = blockIdx.x * 32;
    int h   = blockIdx.y;
    int bb  = blockIdx.z;
    const float* om = g_scratch + OFF_OM;

    // phase 0: offsets + masks
    for (int i = tid; i < 288; i += 128) {
        int p = i / 9, k = i - p * 9;
        size_t base = ((((size_t)bb * 160 + h) * 160) + (w0 + p)) * 27;
        float dy = om[base + 2 * k];
        float dx = om[base + 2 * k + 1];
        float mk = om[base + 18 + k];
        smk[i] = 1.f / (1.f + expf(-mk));
        ssy[i] = (float)h + (float)(k / 3 - 1) + dy;
        ssx[i] = (float)(w0 + p) + (float)(k % 3 - 1) + dx;
    }
    __syncthreads();

    // phase 1: gather. unit = tid>>4 handles (p,k) pairs, c4 = float4 channel grp
    {
        const float* Xb = g_scratch + OFF_X + (size_t)bb * 25600 * 64;
        int c4 = (tid & 15) * 4;
        for (int it = tid >> 4; it < 288; it += 8) {
            int p = it / 9, k = it - p * 9;
            float syv = ssy[p * 9 + k];
            float sxv = ssx[p * 9 + k];
            float mkv = smk[p * 9 + k];
            float fy = floorf(syv), fx = floorf(sxv);
            int iy = (int)fy, ix = (int)fx;
            float ty = syv - fy, tx = sxv - fx;
            float4 r = make_float4(0.f, 0.f, 0.f, 0.f);
            #pragma unroll
            for (int d2 = 0; d2 < 2; d2++) {
                int yy = iy + d2;
                float wy = d2 ? ty : (1.f - ty);
                bool vy = (yy >= 0) && (yy < 160);
                int cy = yy < 0 ? 0 : (yy > 159 ? 159 : yy);
                #pragma unroll
                for (int d3 = 0; d3 < 2; d3++) {
                    int xx = ix + d3;
                    float wx = d3 ? tx : (1.f - tx);
                    bool vx = (xx >= 0) && (xx < 160);
                    int cx = xx < 0 ? 0 : (xx > 159 ? 159 : xx);
                    float wgt = wy * wx * ((vy && vx) ? 1.f : 0.f);
                    float4 gv = __ldg((const float4*)(Xb + ((size_t)cy * 160 + cx) * 64 + c4));
                    r.x += gv.x * wgt; r.y += gv.y * wgt;
                    r.z += gv.z * wgt; r.w += gv.w * wgt;
                }
            }
            r.x *= mkv; r.y *= mkv; r.z *= mkv; r.w *= mkv;
            *(float4*)(val + (size_t)(k * 32 + p) * 68 + c4) = r;
        }
    }
    __syncthreads();

    // phase 2: GEMM. o tile = (tid&15)*4, px tile = (tid>>4)*4
    int o0 = (tid & 15) * 4;
    int pb = (tid >> 4) * 4;
    float acc[4][4];
    #pragma unroll
    for (int j = 0; j < 4; j++)
        #pragma unroll
        for (int i = 0; i < 4; i++) acc[j][i] = 0.f;

    const float* wt = g_scratch + OFF_WT;
    #pragma unroll
    for (int k = 0; k < 9; k++) {
        const float* vrow = val + (size_t)(k * 32 + pb) * 68;
        const float* wk   = wt + (size_t)k * 64 * 64 + o0;
        #pragma unroll 2
        for (int c = 0; c < 64; c++) {
            float4 wv = __ldg((const float4*)(wk + c * 64));
            float v0 = vrow[c];
            float v1 = vrow[68 + c];
            float v2 = vrow[136 + c];
            float v3 = vrow[204 + c];
            acc[0][0] += v0 * wv.x; acc[0][1] += v0 * wv.y; acc[0][2] += v0 * wv.z; acc[0][3] += v0 * wv.w;
            acc[1][0] += v1 * wv.x; acc[1][1] += v1 * wv.y; acc[1][2] += v1 * wv.z; acc[1][3] += v1 * wv.w;
            acc[2][0] += v2 * wv.x; acc[2][1] += v2 * wv.y; acc[2][2] += v2 * wv.z; acc[2][3] += v2 * wv.w;
            acc[3][0] += v3 * wv.x; acc[3][1] += v3 * wv.y; acc[3][2] += v3 * wv.z; acc[3][3] += v3 * wv.w;
        }
    }

    // phase 3: BN + relu, float4 stores along px
    #pragma unroll
    for (int i = 0; i < 4; i++) {
        int o = o0 + i;
        float sc = __ldg(gf + o) * rsqrtf(__ldg(vf + o) + 1e-5f);
        float bi = __ldg(bfp + o) - __ldg(mf + o) * sc;
        float4 ov;
        ov.x = fmaxf(acc[0][i] * sc + bi, 0.f);
        ov.y = fmaxf(acc[1][i] * sc + bi, 0.f);
        ov.z = fmaxf(acc[2][i] * sc + bi, 0.f);
        ov.w = fmaxf(acc[3][i] * sc + bi, 0.f);
        *(float4*)(out + ((size_t)bb * 64 + o) * 25600 + h * 160 + w0 + pb) = ov;
    }
}

// ---------------------------------------------------------------------------
// launch
// ---------------------------------------------------------------------------
extern "C" void kernel_launch(void* const* d_in, const int* in_sizes, int n_in,
                              void* d_out, int out_size) {
    const float* f0 = (const float*)d_in[0];
    const float* f1 = (const float*)d_in[1];
    const float* f2 = (const float*)d_in[2];
    const float* f3 = (const float*)d_in[3];
    const float* w0 = (const float*)d_in[4];
    const float* g0 = (const float*)d_in[5];
    const float* b0 = (const float*)d_in[6];
    const float* m0 = (const float*)d_in[7];
    const float* v0 = (const float*)d_in[8];
    const float* w1 = (const float*)d_in[9];
    const float* g1 = (const float*)d_in[10];
    const float* b1 = (const float*)d_in[11];
    const float* m1 = (const float*)d_in[12];
    const float* v1 = (const float*)d_in[13];
    const float* w2 = (const float*)d_in[14];
    const float* g2 = (const float*)d_in[15];
    const float* b2 = (const float*)d_in[16];
    const float* m2 = (const float*)d_in[17];
    const float* v2 = (const float*)d_in[18];
    const float* w3 = (const float*)d_in[19];
    const float* g3 = (const float*)d_in[20];
    const float* b3 = (const float*)d_in[21];
    const float* m3 = (const float*)d_in[22];
    const float* v3 = (const float*)d_in[23];
    const float* off_w = (const float*)d_in[24];
    const float* off_b = (const float*)d_in[25];
    const float* dcn_w = (const float*)d_in[26];
    const float* gf = (const float*)d_in[27];
    const float* bf = (const float*)d_in[28];
    const float* mf = (const float*)d_in[29];
    const float* vf = (const float*)d_in[30];
    float* out = (float*)d_out;

    float* scratch = nullptr;
    cudaGetSymbolAddress((void**)&scratch, g_scratch);

    cudaFuncSetAttribute(offconv_v2, cudaFuncAttributeMaxDynamicSharedMemorySize, OFFC_SMEM);
    cudaFuncSetAttribute(dcn_v2, cudaFuncAttributeMaxDynamicSharedMemorySize, DCN_SMEM);

    conv1x1_bn_v2<<<dim3(400, 4), 256>>>(f0, w0, g0, b0, m0, v0, scratch + OFF_Y0, 64, 25600);
    conv1x1_bn_v2<<<dim3(100, 4), 256>>>(f1, w1, g1, b1, m1, v1, scratch + OFF_Y1, 128, 6400);
    conv1x1_bn_v2<<<dim3(25, 4), 256>>>(f2, w2, g2, b2, m2, v2, scratch + OFF_Y2, 256, 1600);
    conv1x1_bn_v2<<<dim3(7, 4), 256>>>(f3, w3, g3, b3, m3, v3, scratch + OFF_Y3, 512, 400);

    fuse_v2<<<25600, 64>>>();

    wtrans_v2<<<144, 256>>>(dcn_w);

    offconv_v2<<<dim3(5, 160, 4), 128, OFFC_SMEM>>>(off_w, off_b);

    dcn_v2<<<dim3(5, 160, 4), 128, DCN_SMEM>>>(gf, bf, mf, vf, out);
}